// round 4
// baseline (speedup 1.0000x reference)
#include <cuda_runtime.h>
#include <cstdint>

// Problem constants
#define C_IN      128
#define H_IN      112
#define W_IN      112
#define N_BATCH   8
#define HO_OUT    56
#define WO_OUT    56

// Tiling
#define TILE_WO   28          // half an output row per block
#define NTHREADS  256
#define ROW_S     58          // smem cols per row: 2*28+2 (covers 57 needed + 1 pad)
#define CH_STRIDE 175         // 3*58 + 1 pad (per-channel smem stride, floats)

#define SMEM_X_FLOATS  (C_IN * CH_STRIDE)        // 22400
#define RED_FLOATS     (8 * 9 * TILE_WO)         // 2016 (8 warp-partials)
#define SIG_FLOATS     (9 * TILE_WO)             // 252
#define SMEM_BYTES     ((SMEM_X_FLOATS + RED_FLOATS + SIG_FLOATS) * 4)  // 98,672 B

__global__ __launch_bounds__(NTHREADS, 2)
void pasa_fused_kernel(const float* __restrict__ x,
                       const float* __restrict__ cw,     // (9,128,3,3)
                       const float* __restrict__ bnw,
                       const float* __restrict__ bnb,
                       const float* __restrict__ bnm,
                       const float* __restrict__ bnv,
                       float* __restrict__ out)
{
    extern __shared__ float sm[];
    float* sx   = sm;                        // [128][3][58] (padded)
    float* sred = sm + SMEM_X_FLOATS;        // [8 warps][9 k][28 wo]
    float* ssig = sred + RED_FLOATS;         // [9 k][28 wo]

    const int b   = blockIdx.x;              // 0..895
    const int wt  = b & 1;                   // which half-row
    const int ho  = (b >> 1) % HO_OUT;
    const int n   = b / (2 * HO_OUT);
    const int wo0 = wt * TILE_WO;
    const int t   = threadIdx.x;

    const float* xn = x + (size_t)n * C_IN * H_IN * W_IN;

    // ---------------- Stage x tile: 128 ch x 3 rows x 58 cols (reflect pad) ----
    const int h0 = 2 * ho - 1;               // first input row (may be -1)
    const int c0 = 2 * wo0 - 1;              // first input col (may be -1 / reach 112)
    for (int idx = t; idx < C_IN * 3 * ROW_S; idx += NTHREADS) {
        int c   = idx / (3 * ROW_S);
        int rem = idx - c * (3 * ROW_S);
        int r   = rem / ROW_S;
        int s   = rem - r * ROW_S;
        int rr = h0 + r;  if (rr < 0) rr = -rr;  if (rr > H_IN - 1) rr = 2 * (H_IN - 1) - rr;
        int cc = c0 + s;  if (cc < 0) cc = -cc;  if (cc > W_IN - 1) cc = 2 * (W_IN - 1) - cc;
        sx[c * CH_STRIDE + r * ROW_S + s] = xn[(c * H_IN + rr) * W_IN + cc];
    }
    __syncthreads();

    // ---------------- Sigma conv: 9 outputs, 128-channel reduction --------------
    // thread = (wg = t&3 : 4 groups of 7 wo) x (cg = t>>2 : 64 groups of 2 ch)
    const int wg = t & 3;
    const int cg = t >> 2;

    float acc[9][7];
#pragma unroll
    for (int k = 0; k < 9; k++)
#pragma unroll
        for (int u = 0; u < 7; u++) acc[k][u] = 0.0f;

    const int xbase = wg * 14;               // 7 wos span 15 cols starting here
#pragma unroll
    for (int cc2 = 0; cc2 < 2; cc2++) {
        const int c = cg * 2 + cc2;
        const float* wp = cw + c * 9;        // cw flat: k*1152 + c*9 + i*3 + j
        const float* xc = sx + c * CH_STRIDE + xbase;
#pragma unroll
        for (int i = 0; i < 3; i++) {
            float xr[15];
#pragma unroll
            for (int s = 0; s < 15; s++) xr[s] = xc[i * ROW_S + s];
#pragma unroll
            for (int k = 0; k < 9; k++) {
#pragma unroll
                for (int j = 0; j < 3; j++) {
                    const float w = __ldg(wp + k * 1152 + i * 3 + j);
#pragma unroll
                    for (int u = 0; u < 7; u++)
                        acc[k][u] = fmaf(xr[2 * u + j], w, acc[k][u]);
                }
            }
        }
    }

    // Reduce across cg low-3-bits (lane bits 2,3,4) with butterflies
#pragma unroll
    for (int k = 0; k < 9; k++)
#pragma unroll
        for (int u = 0; u < 7; u++) {
            float v = acc[k][u];
            v += __shfl_xor_sync(0xffffffffu, v, 4);
            v += __shfl_xor_sync(0xffffffffu, v, 8);
            v += __shfl_xor_sync(0xffffffffu, v, 16);
            acc[k][u] = v;
        }
    const int warp = t >> 5;
    if ((t & 28) == 0) {                     // lanes 0..3 of each warp (one per wg)
#pragma unroll
        for (int k = 0; k < 9; k++)
#pragma unroll
            for (int u = 0; u < 7; u++)
                sred[(warp * 9 + k) * TILE_WO + wg * 7 + u] = acc[k][u];
    }
    __syncthreads();

    // ---------------- Final 8-way reduce + frozen-BN + clamp --------------------
    if (t < 9 * TILE_WO) {
        const int k = t / TILE_WO, wol = t - k * TILE_WO;
        float s = 0.0f;
#pragma unroll
        for (int w8 = 0; w8 < 8; w8++) s += sred[(w8 * 9 + k) * TILE_WO + wol];
        const float scale = bnw[k] * rsqrtf(bnv[k] + 1e-5f);
        const float shift = bnb[k] - bnm[k] * scale;
        s = fmaf(s, scale, shift);
        s = fmaxf(s, 1e-4f);
        ssig[k * TILE_WO + wol] = s;
    }
    __syncthreads();

    // ---------------- Normalize over the 9 taps ---------------------------------
    if (t < TILE_WO) {
        float sum = 0.0f;
#pragma unroll
        for (int k = 0; k < 9; k++) sum += ssig[k * TILE_WO + t];
        const float inv = 1.0f / sum;
#pragma unroll
        for (int k = 0; k < 9; k++) ssig[k * TILE_WO + t] *= inv;
    }
    __syncthreads();

    // ---------------- Apply: out[c][wo] = sum_k x_window * sigma ----------------
    float* ob = out + (size_t)n * C_IN * HO_OUT * WO_OUT + (size_t)ho * WO_OUT + wo0;
    for (int idx = t; idx < C_IN * TILE_WO; idx += NTHREADS) {
        const int c   = idx / TILE_WO;
        const int wol = idx - c * TILE_WO;
        const float* xc = sx + c * CH_STRIDE + 2 * wol;
        float r = 0.0f;
#pragma unroll
        for (int i = 0; i < 3; i++)
#pragma unroll
            for (int j = 0; j < 3; j++)
                r = fmaf(xc[i * ROW_S + j], ssig[(i * 3 + j) * TILE_WO + wol], r);
        ob[(size_t)c * HO_OUT * WO_OUT + wol] = r;
    }
}

extern "C" void kernel_launch(void* const* d_in, const int* in_sizes, int n_in,
                              void* d_out, int out_size)
{
    const float* x   = (const float*)d_in[0];
    const float* cw  = (const float*)d_in[1];
    const float* bnw = (const float*)d_in[2];
    const float* bnb = (const float*)d_in[3];
    const float* bnm = (const float*)d_in[4];
    const float* bnv = (const float*)d_in[5];
    float* out = (float*)d_out;

    cudaFuncSetAttribute(pasa_fused_kernel,
                         cudaFuncAttributeMaxDynamicSharedMemorySize, SMEM_BYTES);

    const int grid = N_BATCH * HO_OUT * 2;   // 896 blocks
    pasa_fused_kernel<<<grid, NTHREADS, SMEM_BYTES>>>(x, cw, bnw, bnb, bnm, bnv, out);
}

// round 7
// speedup vs baseline: 1.4436x; 1.4436x over previous
#include <cuda_runtime.h>
#include <cstdint>

// Problem constants
#define C_IN      128
#define H_IN      112
#define W_IN      112
#define N_BATCH   8
#define HO_OUT    56
#define WO_OUT    56

// Tiling
#define TILE_WO   28
#define NTHREADS  256
#define ROW_S     58          // 2*28+2
#define CH_STRIDE 175         // 3*58 + 1 pad

#define SMEM_X_FLOATS  (C_IN * CH_STRIDE)        // 22400
#define RED_FLOATS     (16 * 9 * TILE_WO)        // 4032 (16 partials)
#define SIG_FLOATS     (9 * TILE_WO)             // 252
#define SMEM_BYTES     ((SMEM_X_FLOATS + RED_FLOATS + SIG_FLOATS) * 4)  // 106,736 B

// Repacked weights: [c][i*3+j][12] (k contiguous, padded 9->12 for LDG.128)
__device__ __align__(16) float g_wpk[C_IN * 9 * 12];
__device__ float g_scale[9];
__device__ float g_shift[9];

__global__ void repack_kernel(const float* __restrict__ cw,
                              const float* __restrict__ bnw,
                              const float* __restrict__ bnb,
                              const float* __restrict__ bnm,
                              const float* __restrict__ bnv)
{
    int idx = blockIdx.x * blockDim.x + threadIdx.x;
    if (idx < C_IN * 81) {
        int c  = idx / 81;
        int r  = idx - c * 81;
        int k  = r / 9;
        int ij = r - k * 9;
        g_wpk[(c * 9 + ij) * 12 + k] = cw[(k * C_IN + c) * 9 + ij];
    }
    if (idx < 9) {
        float sc = bnw[idx] * rsqrtf(bnv[idx] + 1e-5f);
        g_scale[idx] = sc;
        g_shift[idx] = bnb[idx] - bnm[idx] * sc;
    }
}

// ---- f32x2 helpers (sm_103a packed fp32) ------------------------------------
__device__ __forceinline__ unsigned long long pk2(float v) {
    unsigned long long r;
    asm("mov.b64 %0, {%1, %1};" : "=l"(r) : "f"(v));
    return r;
}
__device__ __forceinline__ void ffma2(unsigned long long& d,
                                      unsigned long long a, unsigned long long b) {
    asm("fma.rn.f32x2 %0, %1, %2, %0;" : "+l"(d) : "l"(a), "l"(b));
}
__device__ __forceinline__ unsigned long long add2(unsigned long long a,
                                                   unsigned long long b) {
    unsigned long long r;
    asm("add.rn.f32x2 %0, %1, %2;" : "=l"(r) : "l"(a), "l"(b));
    return r;
}
__device__ __forceinline__ void unpk(unsigned long long v, float& lo, float& hi) {
    asm("mov.b64 {%0, %1}, %2;" : "=f"(lo), "=f"(hi) : "l"(v));
}
__device__ __forceinline__ void cp_async4(unsigned saddr, const float* gaddr) {
    asm volatile("cp.async.ca.shared.global [%0], [%1], 4;\n"
                 :: "r"(saddr), "l"(gaddr));
}

__global__ __launch_bounds__(NTHREADS, 2)
void pasa_fused_kernel(const float* __restrict__ x, float* __restrict__ out)
{
    extern __shared__ float sm[];
    float* sx   = sm;                        // [128][3][58] (pad stride 175)
    float* sred = sm + SMEM_X_FLOATS;        // [16 part][9 k][28 wo]
    float* ssig = sred + RED_FLOATS;         // [9 k][28 wo]

    const int b   = blockIdx.x;              // 0..895
    const int wt  = b & 1;
    const int ho  = (b >> 1) % HO_OUT;
    const int n   = b / (2 * HO_OUT);
    const int wo0 = wt * TILE_WO;
    const int t   = threadIdx.x;

    const float* xn = x + (size_t)n * C_IN * H_IN * W_IN;

    // ---------------- Stage x tile via cp.async (reflect pad precomputed) ------
    const int h0 = 2 * ho - 1;
    const int c0 = 2 * wo0 - 1;
    if (t < 3 * ROW_S) {                     // 174 active threads
        const int r = t / ROW_S;
        const int s = t - r * ROW_S;
        int rr = h0 + r;  if (rr < 0) rr = -rr;   // upper edge can't overflow
        int cc = c0 + s;  if (cc < 0) cc = -cc;  if (cc > W_IN - 1) cc = 2 * (W_IN - 1) - cc;
        const float* gp = xn + rr * W_IN + cc;
        unsigned sa = (unsigned)__cvta_generic_to_shared(sx + r * ROW_S + s);
#pragma unroll 8
        for (int c = 0; c < C_IN; c++)
            cp_async4(sa + (unsigned)(c * CH_STRIDE * 4), gp + (size_t)c * (H_IN * W_IN));
    }
    asm volatile("cp.async.commit_group;\n" ::: "memory");
    asm volatile("cp.async.wait_group 0;\n" ::: "memory");
    __syncthreads();

    // ---------------- Sigma conv: FFMA2, k packed in pairs ----------------------
    // thread = (wg = t&3 : 4 groups of 7 wo) x (cg = t>>2 : 64 groups of 2 ch)
    const int wg = t & 3;
    const int cg = t >> 2;

    unsigned long long A0[7], A1[7], A2[7], A3[7];   // k pairs (0,1)(2,3)(4,5)(6,7)
    float A8[7];                                     // k = 8
#pragma unroll
    for (int u = 0; u < 7; u++) { A0[u] = 0ull; A1[u] = 0ull; A2[u] = 0ull; A3[u] = 0ull; A8[u] = 0.0f; }

    const int xbase = wg * 14;
#pragma unroll
    for (int cc2 = 0; cc2 < 2; cc2++) {
        const int c = cg * 2 + cc2;
        const float* wrow = g_wpk + c * 108;
        const float* xc   = sx + c * CH_STRIDE + xbase;
#pragma unroll
        for (int i = 0; i < 3; i++) {
            float xr[15];
#pragma unroll
            for (int s = 0; s < 15; s++) xr[s] = xc[i * ROW_S + s];
#pragma unroll
            for (int j = 0; j < 3; j++) {
                const int off = (i * 3 + j) * 12;
                const ulonglong2 pA = *reinterpret_cast<const ulonglong2*>(wrow + off);      // (w0,w1)(w2,w3)
                const ulonglong2 pB = *reinterpret_cast<const ulonglong2*>(wrow + off + 4);  // (w4,w5)(w6,w7)
                const float      w8 = wrow[off + 8];
#pragma unroll
                for (int u = 0; u < 7; u++) {
                    const float xv = xr[2 * u + j];
                    const unsigned long long x2 = pk2(xv);
                    ffma2(A0[u], x2, pA.x);
                    ffma2(A1[u], x2, pA.y);
                    ffma2(A2[u], x2, pB.x);
                    ffma2(A3[u], x2, pB.y);
                    A8[u] = fmaf(xv, w8, A8[u]);
                }
            }
        }
    }

    // ---------------- 2-level butterfly (lane bits 2,3) -------------------------
#pragma unroll
    for (int u = 0; u < 7; u++) {
        unsigned long long v;
        v = A0[u]; v = add2(v, __shfl_xor_sync(0xffffffffu, v, 4)); v = add2(v, __shfl_xor_sync(0xffffffffu, v, 8)); A0[u] = v;
        v = A1[u]; v = add2(v, __shfl_xor_sync(0xffffffffu, v, 4)); v = add2(v, __shfl_xor_sync(0xffffffffu, v, 8)); A1[u] = v;
        v = A2[u]; v = add2(v, __shfl_xor_sync(0xffffffffu, v, 4)); v = add2(v, __shfl_xor_sync(0xffffffffu, v, 8)); A2[u] = v;
        v = A3[u]; v = add2(v, __shfl_xor_sync(0xffffffffu, v, 4)); v = add2(v, __shfl_xor_sync(0xffffffffu, v, 8)); A3[u] = v;
        float f = A8[u];
        f += __shfl_xor_sync(0xffffffffu, f, 4);
        f += __shfl_xor_sync(0xffffffffu, f, 8);
        A8[u] = f;
    }

    // Lanes {0..3, 16..19} of each warp hold sums over 4 cg (= 8 channels)
    if ((t & 12) == 0) {
        const int p = ((t >> 5) << 1) + ((t >> 4) & 1);  // 16 partials
        float* rp = sred + p * 252 + wg * 7;             // [p][k][wol] -> p*252 + k*28 + wg*7+u
        float lo, hi;
#pragma unroll
        for (int u = 0; u < 7; u++) {
            unpk(A0[u], lo, hi); rp[0 * 28 + u] = lo; rp[1 * 28 + u] = hi;
            unpk(A1[u], lo, hi); rp[2 * 28 + u] = lo; rp[3 * 28 + u] = hi;
            unpk(A2[u], lo, hi); rp[4 * 28 + u] = lo; rp[5 * 28 + u] = hi;
            unpk(A3[u], lo, hi); rp[6 * 28 + u] = lo; rp[7 * 28 + u] = hi;
            rp[8 * 28 + u] = A8[u];
        }
    }
    __syncthreads();

    // ---------------- 16-way reduce + frozen-BN + clamp -------------------------
    if (t < 9 * TILE_WO) {                   // t = k*28 + wol
        float s = 0.0f;
#pragma unroll
        for (int p = 0; p < 16; p++) s += sred[p * 252 + t];
        const int k = t / TILE_WO;
        s = fmaf(s, g_scale[k], g_shift[k]);
        s = fmaxf(s, 1e-4f);
        ssig[t] = s;
    }
    __syncthreads();

    // ---------------- Normalize over the 9 taps ---------------------------------
    if (t < TILE_WO) {
        float sum = 0.0f;
#pragma unroll
        for (int k = 0; k < 9; k++) sum += ssig[k * TILE_WO + t];
        const float inv = 1.0f / sum;
#pragma unroll
        for (int k = 0; k < 9; k++) ssig[k * TILE_WO + t] *= inv;
    }
    __syncthreads();

    // ---------------- Apply: 224 threads, sigma hoisted to registers ------------
    if (t < 8 * TILE_WO) {
        const int cl  = t / TILE_WO;         // 0..7
        const int wol = t - cl * TILE_WO;    // 0..27
        float sig[9];
#pragma unroll
        for (int k = 0; k < 9; k++) sig[k] = ssig[k * TILE_WO + wol];

        const float* xc = sx + cl * CH_STRIDE + 2 * wol;
        float* ob = out + ((size_t)n * C_IN + cl) * (HO_OUT * WO_OUT)
                        + (size_t)ho * WO_OUT + wo0 + wol;
#pragma unroll 4
        for (int it = 0; it < 16; it++) {
            float r = 0.0f;
#pragma unroll
            for (int i = 0; i < 3; i++)
#pragma unroll
                for (int j = 0; j < 3; j++)
                    r = fmaf(xc[i * ROW_S + j], sig[i * 3 + j], r);
            *ob = r;
            xc += 8 * CH_STRIDE;
            ob += (size_t)8 * HO_OUT * WO_OUT;
        }
    }
}

extern "C" void kernel_launch(void* const* d_in, const int* in_sizes, int n_in,
                              void* d_out, int out_size)
{
    const float* x   = (const float*)d_in[0];
    const float* cw  = (const float*)d_in[1];
    const float* bnw = (const float*)d_in[2];
    const float* bnb = (const float*)d_in[3];
    const float* bnm = (const float*)d_in[4];
    const float* bnv = (const float*)d_in[5];
    float* out = (float*)d_out;

    repack_kernel<<<(C_IN * 81 + 255) / 256, 256>>>(cw, bnw, bnb, bnm, bnv);

    cudaFuncSetAttribute(pasa_fused_kernel,
                         cudaFuncAttributeMaxDynamicSharedMemorySize, SMEM_BYTES);
    const int grid = N_BATCH * HO_OUT * 2;   // 896 blocks
    pasa_fused_kernel<<<grid, NTHREADS, SMEM_BYTES>>>(x, out);
}